// round 9
// baseline (speedup 1.0000x reference)
#include <cuda_runtime.h>

// ---------------- problem constants ----------------
#define NSEQ  704          // B*F
#define TT    512
#define HDIM  64
#define GDIM  192          // 3*H
#define MROWS (NSEQ*TT)    // 360448
#define RSPC  5            // sequences per recur CTA (both dirs)
#define NCTA_R 141         // ceil(704/5) <= 148 -> one CTA per SM

// ---------------- scratch (device globals; no allocation) ----------------
__device__ float g_pre[(size_t)2 * MROWS * GDIM];   // [dir][row][192]
__device__ float g_hbuf[(size_t)MROWS * 128];       // [row][2*H]

typedef unsigned long long u64;

__device__ __forceinline__ u64 fma2(u64 a, u64 b, u64 c) {
    u64 d;
    asm("fma.rn.f32x2 %0, %1, %2, %3;" : "=l"(d) : "l"(a), "l"(b), "l"(c));
    return d;
}
__device__ __forceinline__ float2 u2f(u64 v) {
    float2 r;
    asm("mov.b64 {%0,%1}, %2;" : "=f"(r.x), "=f"(r.y) : "l"(v));
    return r;
}
__device__ __forceinline__ float tanh_fast(float x) {
    float y;
    asm("tanh.approx.f32 %0, %1;" : "=f"(y) : "f"(x));
    return y;
}
__device__ __forceinline__ float sig_fast(float x) {
    return 0.5f * tanh_fast(0.5f * x) + 0.5f;
}
__device__ __forceinline__ float sig_acc(float x) {
    return __fdividef(1.f, 1.f + __expf(-x));
}

// ---------------- layer-0 projection (KD=64): 2 gate rows per thread ----------------
// 192 threads = 384 gate rows (both dirs). W rows j0=2*tid, j0+1 in 64 u64 regs.
// x chunks (32 rows x 64 floats, contiguous) double-buffered in smem; broadcast LDS.
// Per x row: 16 LDS.128 + 64 fma2  (1:4 issue ratio).
__global__ __launch_bounds__(192, 2)
void proj0_kernel(const float* __restrict__ xin,
                  const float* __restrict__ W,     // [384][64]
                  const float* __restrict__ bias)  // [384]
{
    const int tid  = threadIdx.x;
    const int row0 = blockIdx.x * 256;

    __shared__ __align__(16) float xs[2][32 * 64];

    const int j0 = 2 * tid;
    const int d  = (j0 >= GDIM) ? 1 : 0;
    const int g0 = j0 - d * GDIM;

    u64 w[2][32];
    const u64* wr = (const u64*)(W + (size_t)j0 * 64);
#pragma unroll
    for (int q = 0; q < 32; q++) { w[0][q] = wr[q]; w[1][q] = wr[32 + q]; }
    const float2 b2 = *(const float2*)(bias + j0);

    float* op = g_pre + ((size_t)d * MROWS + row0) * GDIM + g0;

    {   // chunk 0 (contiguous copy)
        const float4* s4 = (const float4*)(xin + (size_t)row0 * 64);
        for (int i = tid; i < 512; i += 192) ((float4*)xs[0])[i] = s4[i];
    }
    __syncthreads();

#pragma unroll 1
    for (int c = 0; c < 8; c++) {
        const int buf = c & 1;
        if (c < 7) {
            const float4* s4 = (const float4*)(xin + (size_t)(row0 + (c + 1) * 32) * 64);
            for (int i = tid; i < 512; i += 192) ((float4*)xs[buf ^ 1])[i] = s4[i];
        }
#pragma unroll 1
        for (int r = 0; r < 32; r++) {
            const ulonglong2* xp = (const ulonglong2*)(xs[buf] + r * 64);
            u64 a0 = 0, a1 = 0, a2 = 0, a3 = 0;
#pragma unroll
            for (int q = 0; q < 16; q++) {
                ulonglong2 v = xp[q];
                a0 = fma2(w[0][2 * q + 0], v.x, a0);
                a1 = fma2(w[0][2 * q + 1], v.y, a1);
                a2 = fma2(w[1][2 * q + 0], v.x, a2);
                a3 = fma2(w[1][2 * q + 1], v.y, a3);
            }
            float2 f0 = u2f(a0), f1 = u2f(a1), f2_ = u2f(a2), f3 = u2f(a3);
            float s0 = (f0.x + f0.y) + (f1.x + f1.y) + b2.x;
            float s1 = (f2_.x + f2_.y) + (f3.x + f3.y) + b2.y;
            *(float2*)(op + (size_t)(c * 32 + r) * GDIM) = make_float2(s0, s1);
        }
        __syncthreads();
    }
}

// ---------------- layer-1 projection (KD=128): split-K, 2 rows per thread-pair ----------------
// 384 threads; m=tid/2 picks rows 2m,2m+1; kh=tid&1 picks K-half (64 floats = 32 u64 regs/row).
// Partner halves combined with shfl_xor(1). x halves padded (+4 floats) for bank-disjoint LDS.
__global__ __launch_bounds__(384)
void proj1_kernel(const float* __restrict__ W,     // [384][128]
                  const float* __restrict__ bias)  // [384]
{
    const float* in = (const float*)g_hbuf;
    const int tid  = threadIdx.x;
    const int row0 = blockIdx.x * 256;

    __shared__ __align__(16) float xs[2][32 * 132];   // 132 = 64 + 4 pad + 64

    const int m  = tid >> 1;
    const int kh = tid & 1;
    const int j0 = 2 * m;
    const int d  = (j0 >= GDIM) ? 1 : 0;
    const int g0 = j0 - d * GDIM;

    u64 w[2][32];
    const u64* wr = (const u64*)(W + (size_t)j0 * 128);
#pragma unroll
    for (int q = 0; q < 32; q++) {
        w[0][q] = wr[kh * 32 + q];
        w[1][q] = wr[64 + kh * 32 + q];
    }
    const float2 b2 = *(const float2*)(bias + j0);

    float* op = g_pre + ((size_t)d * MROWS + row0) * GDIM + g0;

    auto load_chunk = [&](int c, int buf) {
        const float4* s4 = (const float4*)(in + (size_t)(row0 + c * 32) * 128);
        for (int i = tid; i < 1024; i += 384) {
            int r = i >> 5, jj = i & 31;
            int dstf = r * 132 + ((jj < 16) ? jj * 4 : 68 + (jj - 16) * 4);
            *(float4*)(xs[buf] + dstf) = s4[i];
        }
    };

    load_chunk(0, 0);
    __syncthreads();

#pragma unroll 1
    for (int c = 0; c < 8; c++) {
        const int buf = c & 1;
        if (c < 7) load_chunk(c + 1, buf ^ 1);
#pragma unroll 1
        for (int r = 0; r < 32; r++) {
            const ulonglong2* xp = (const ulonglong2*)(xs[buf] + r * 132 + kh * 68);
            u64 a0 = 0, a1 = 0, a2 = 0, a3 = 0;
#pragma unroll
            for (int q = 0; q < 16; q++) {
                ulonglong2 v = xp[q];
                a0 = fma2(w[0][2 * q + 0], v.x, a0);
                a1 = fma2(w[0][2 * q + 1], v.y, a1);
                a2 = fma2(w[1][2 * q + 0], v.x, a2);
                a3 = fma2(w[1][2 * q + 1], v.y, a3);
            }
            float2 f0 = u2f(a0), f1 = u2f(a1), f2_ = u2f(a2), f3 = u2f(a3);
            float s0 = (f0.x + f0.y) + (f1.x + f1.y);
            float s1 = (f2_.x + f2_.y) + (f3.x + f3.y);
            s0 += __shfl_xor_sync(0xffffffffu, s0, 1);
            s1 += __shfl_xor_sync(0xffffffffu, s1, 1);
            if (kh == 0)
                *(float2*)(op + (size_t)(c * 32 + r) * GDIM) =
                    make_float2(s0 + b2.x, s1 + b2.y);
        }
        __syncthreads();
    }
}

// ---------------- recurrence: both dirs, 2 gates/thread, 5 seqs/CTA ----------------
// 192 threads: dir = tid/96 (warp-uniform), gates g0=2*(tid%96), g0+1.
// Whh rows in 128 regs; per seq per step: 16 broadcast LDS + 64 fma2.
__global__ __launch_bounds__(192)
void recur_kernel(const float* __restrict__ Whh,   // [2][192][64]
                  const float* __restrict__ bhh)   // [2][192]
{
    const int n0  = blockIdx.x * RSPC;
    const int tid = threadIdx.x;
    const int d   = tid / 96;
    const int g0  = 2 * (tid % 96);

    __shared__ float h_sh[2][RSPC][64];
    __shared__ float s_v[RSPC][2][256];

    u64 w[2][32];
    const u64* wr = (const u64*)(Whh + ((size_t)d * GDIM + g0) * HDIM);
#pragma unroll
    for (int q = 0; q < 32; q++) { w[0][q] = wr[q]; w[1][q] = wr[32 + q]; }
    const float2 bh = *(const float2*)(bhh + d * GDIM + g0);

    for (int i = tid; i < 2 * RSPC * 64; i += 192) ((float*)h_sh)[i] = 0.f;
    __syncthreads();

    const int t0 = d ? (TT - 1) : 0;
    const int dt = d ? -1 : 1;
    const long dtG = (long)dt * GDIM;

    const float* pcur[RSPC];
#pragma unroll
    for (int q = 0; q < RSPC; q++) {
        int n = n0 + q; if (n >= NSEQ) n = NSEQ - 1;
        pcur[q] = g_pre + ((size_t)d * MROWS + (size_t)n * TT + t0) * GDIM + g0;
    }

    float2 pc[RSPC];
#pragma unroll
    for (int q = 0; q < RSPC; q++) {
        pc[q] = __ldg((const float2*)pcur[q]);
        pcur[q] += dtG;
    }

#pragma unroll 1
    for (int s = 0; s < TT; s++) {
        float2 pn[RSPC];
        if (s < TT - 1) {
#pragma unroll
            for (int q = 0; q < RSPC; q++) {
                pn[q] = __ldg((const float2*)pcur[q]);
                pcur[q] += dtG;
            }
        }

        // phase A: hh dots for 2 gates x 5 seqs
#pragma unroll 1
        for (int seq = 0; seq < RSPC; seq++) {
            const ulonglong2* h2 = (const ulonglong2*)h_sh[d][seq];
            u64 a0 = 0, a1 = 0, a2 = 0, a3 = 0;
#pragma unroll
            for (int q = 0; q < 16; q++) {
                ulonglong2 v = h2[q];
                a0 = fma2(w[0][2 * q + 0], v.x, a0);
                a1 = fma2(w[0][2 * q + 1], v.y, a1);
                a2 = fma2(w[1][2 * q + 0], v.x, a2);
                a3 = fma2(w[1][2 * q + 1], v.y, a3);
            }
            float2 f0 = u2f(a0), f1 = u2f(a1), f2_ = u2f(a2), f3 = u2f(a3);
            float hh0 = (f0.x + f0.y) + (f1.x + f1.y) + bh.x;
            float hh1 = (f2_.x + f2_.y) + (f3.x + f3.y) + bh.y;
            float2 pcv = pc[seq];
            if (g0 < 128) {      // r or z gates: store pre+hh
                *(float2*)&s_v[seq][d][g0] = make_float2(hh0 + pcv.x, hh1 + pcv.y);
            } else {             // n gates: keep hh and pre separate
                *(float2*)&s_v[seq][d][g0]      = make_float2(hh0, hh1);
                *(float2*)&s_v[seq][d][g0 + 64] = pcv;
            }
        }
        __syncthreads();

        // phase B: activations, 640 slots over 192 threads
        {
            auto act = [&](int slot) {
                int seq = slot >> 7, rr = slot & 127;
                int dd = rr >> 6, idx = rr & 63;
                const float* sv = s_v[seq][dd];
                float r    = sig_fast(sv[idx]);
                float z    = sig_fast(sv[64 + idx]);
                float nn   = tanh_fast(sv[192 + idx] + r * sv[128 + idx]);
                float hold = h_sh[dd][seq][idx];
                float hnew = nn + z * (hold - nn);
                h_sh[dd][seq][idx] = hnew;
                int n = n0 + seq;
                if (n < NSEQ) {
                    int td = dd ? (TT - 1 - s) : s;
                    g_hbuf[((size_t)n * TT + td) * 128 + dd * 64 + idx] = hnew;
                }
            };
            act(tid);
            act(tid + 192);
            act(tid + 384);
            if (tid < 64) act(tid + 576);
        }
        __syncthreads();

#pragma unroll
        for (int q = 0; q < RSPC; q++) pc[q] = pn[q];
    }
}

// ---------------- FC head: 2 outputs per warp (MLP=2) ----------------
__global__ void fc_kernel(const float* __restrict__ fcw,
                          const float* __restrict__ fcb,
                          float* __restrict__ out)
{
    int wid  = threadIdx.x >> 5;
    int lane = threadIdx.x & 31;
    size_t g0 = (size_t)blockIdx.x * 16 + wid * 2;

    float4 w4 = *(const float4*)(fcw + lane * 4);
    float4 v0 = *(const float4*)(g_hbuf + g0 * 128 + lane * 4);
    float4 v1 = *(const float4*)(g_hbuf + (g0 + 1) * 128 + lane * 4);
    float d0 = v0.x * w4.x + v0.y * w4.y + v0.z * w4.z + v0.w * w4.w;
    float d1 = v1.x * w4.x + v1.y * w4.y + v1.z * w4.z + v1.w * w4.w;
#pragma unroll
    for (int o = 16; o > 0; o >>= 1) {
        d0 += __shfl_down_sync(0xffffffffu, d0, o);
        d1 += __shfl_down_sync(0xffffffffu, d1, o);
    }
    if (lane == 0) {
        float bb = fcb[0];
#pragma unroll
        for (int k = 0; k < 2; k++) {
            size_t g = g0 + k;
            float dv = k ? d1 : d0;
            int nidx = (int)(g / TT), t = (int)(g % TT);
            int b = nidx / 88, f = nidx % 88;
            out[((size_t)b * TT + t) * 88 + f] = sig_acc(dv + bb);
        }
    }
}

// ---------------- launch ----------------
extern "C" void kernel_launch(void* const* d_in, const int* in_sizes, int n_in,
                              void* d_out, int out_size)
{
    const float* x    = (const float*)d_in[0];
    const float* Wih0 = (const float*)d_in[1];
    const float* Whh0 = (const float*)d_in[2];
    const float* bih0 = (const float*)d_in[3];
    const float* bhh0 = (const float*)d_in[4];
    const float* Wih1 = (const float*)d_in[5];
    const float* Whh1 = (const float*)d_in[6];
    const float* bih1 = (const float*)d_in[7];
    const float* bhh1 = (const float*)d_in[8];
    const float* fcw  = (const float*)d_in[9];
    const float* fcb  = (const float*)d_in[10];
    float* out = (float*)d_out;

    proj0_kernel<<<MROWS / 256, 192>>>(x, Wih0, bih0);      // L0 input proj
    recur_kernel<<<NCTA_R, 192>>>(Whh0, bhh0);              // L0 GRU (both dirs)
    proj1_kernel<<<MROWS / 256, 384>>>(Wih1, bih1);         // L1 input proj (reads g_hbuf)
    recur_kernel<<<NCTA_R, 192>>>(Whh1, bhh1);              // L1 GRU (both dirs)
    fc_kernel<<<MROWS / 16, 256>>>(fcw, fcb, out);          // FC + sigmoid
}

// round 11
// speedup vs baseline: 1.2415x; 1.2415x over previous
#include <cuda_runtime.h>

// ---------------- problem constants ----------------
#define NSEQ  704          // B*F
#define TT    512
#define HDIM  64
#define GDIM  192          // 3*H
#define MROWS (NSEQ*TT)    // 360448
#define SPC   5            // sequences per recur CTA (per dir)
#define NCTA_R ((NSEQ + SPC - 1) / SPC)   // 141

// ---------------- scratch (device globals; no allocation) ----------------
__device__ float g_pre[(size_t)2 * MROWS * GDIM];   // [dir][row][192]
__device__ float g_hbuf[(size_t)MROWS * 128];       // [row][2*H]

typedef unsigned long long u64;

__device__ __forceinline__ u64 fma2(u64 a, u64 b, u64 c) {
    u64 d;
    asm("fma.rn.f32x2 %0, %1, %2, %3;" : "=l"(d) : "l"(a), "l"(b), "l"(c));
    return d;
}
__device__ __forceinline__ float2 u2f(u64 v) {
    float2 r;
    asm("mov.b64 {%0,%1}, %2;" : "=f"(r.x), "=f"(r.y) : "l"(v));
    return r;
}
__device__ __forceinline__ float tanh_fast(float x) {
    float y;
    asm("tanh.approx.f32 %0, %1;" : "=f"(y) : "f"(x));
    return y;
}
__device__ __forceinline__ float sig_fast(float x) {
    return 0.5f * tanh_fast(0.5f * x) + 0.5f;
}
__device__ __forceinline__ float sig_acc(float x) {
    return __fdividef(1.f, 1.f + __expf(-x));
}

// ---------------- layer-0 projection (KD=64): 2 gate rows per thread ----------------
// 192 threads = 384 gate rows (both dirs). W rows j0=2*tid, j0+1 in 64 u64 regs.
// x chunks (32 rows x 64 floats, contiguous) double-buffered in smem; broadcast LDS.
// Per x row: 16 LDS.128 + 64 fma2  (1:4 issue ratio).
__global__ __launch_bounds__(192, 2)
void proj0_kernel(const float* __restrict__ xin,
                  const float* __restrict__ W,     // [384][64]
                  const float* __restrict__ bias)  // [384]
{
    const int tid  = threadIdx.x;
    const int row0 = blockIdx.x * 256;

    __shared__ __align__(16) float xs[2][32 * 64];

    const int j0 = 2 * tid;
    const int d  = (j0 >= GDIM) ? 1 : 0;
    const int g0 = j0 - d * GDIM;

    u64 w[2][32];
    const u64* wr = (const u64*)(W + (size_t)j0 * 64);
#pragma unroll
    for (int q = 0; q < 32; q++) { w[0][q] = wr[q]; w[1][q] = wr[32 + q]; }
    const float2 b2 = *(const float2*)(bias + j0);

    float* op = g_pre + ((size_t)d * MROWS + row0) * GDIM + g0;

    {   // chunk 0 (contiguous copy)
        const float4* s4 = (const float4*)(xin + (size_t)row0 * 64);
        for (int i = tid; i < 512; i += 192) ((float4*)xs[0])[i] = s4[i];
    }
    __syncthreads();

#pragma unroll 1
    for (int c = 0; c < 8; c++) {
        const int buf = c & 1;
        if (c < 7) {
            const float4* s4 = (const float4*)(xin + (size_t)(row0 + (c + 1) * 32) * 64);
            for (int i = tid; i < 512; i += 192) ((float4*)xs[buf ^ 1])[i] = s4[i];
        }
#pragma unroll 1
        for (int r = 0; r < 32; r++) {
            const ulonglong2* xp = (const ulonglong2*)(xs[buf] + r * 64);
            u64 a0 = 0, a1 = 0, a2 = 0, a3 = 0;
#pragma unroll
            for (int q = 0; q < 16; q++) {
                ulonglong2 v = xp[q];
                a0 = fma2(w[0][2 * q + 0], v.x, a0);
                a1 = fma2(w[0][2 * q + 1], v.y, a1);
                a2 = fma2(w[1][2 * q + 0], v.x, a2);
                a3 = fma2(w[1][2 * q + 1], v.y, a3);
            }
            float2 f0 = u2f(a0), f1 = u2f(a1), f2_ = u2f(a2), f3 = u2f(a3);
            float s0 = (f0.x + f0.y) + (f1.x + f1.y) + b2.x;
            float s1 = (f2_.x + f2_.y) + (f3.x + f3.y) + b2.y;
            *(float2*)(op + (size_t)(c * 32 + r) * GDIM) = make_float2(s0, s1);
        }
        __syncthreads();
    }
}

// ---------------- layer-1 projection (KD=128): split-K, 2 rows per thread-pair ----------------
// 384 threads; m=tid/2 picks rows 2m,2m+1; kh=tid&1 picks K-half (64 floats = 32 u64 regs/row).
// Partner halves combined with shfl_xor(1). x halves padded (+4 floats) for bank-disjoint LDS.
__global__ __launch_bounds__(384)
void proj1_kernel(const float* __restrict__ W,     // [384][128]
                  const float* __restrict__ bias)  // [384]
{
    const float* in = (const float*)g_hbuf;
    const int tid  = threadIdx.x;
    const int row0 = blockIdx.x * 256;

    __shared__ __align__(16) float xs[2][32 * 132];   // 132 = 64 + 4 pad + 64

    const int m  = tid >> 1;
    const int kh = tid & 1;
    const int j0 = 2 * m;
    const int d  = (j0 >= GDIM) ? 1 : 0;
    const int g0 = j0 - d * GDIM;

    u64 w[2][32];
    const u64* wr = (const u64*)(W + (size_t)j0 * 128);
#pragma unroll
    for (int q = 0; q < 32; q++) {
        w[0][q] = wr[kh * 32 + q];
        w[1][q] = wr[64 + kh * 32 + q];
    }
    const float2 b2 = *(const float2*)(bias + j0);

    float* op = g_pre + ((size_t)d * MROWS + row0) * GDIM + g0;

    auto load_chunk = [&](int c, int buf) {
        const float4* s4 = (const float4*)(in + (size_t)(row0 + c * 32) * 128);
        for (int i = tid; i < 1024; i += 384) {
            int r = i >> 5, jj = i & 31;
            int dstf = r * 132 + ((jj < 16) ? jj * 4 : 68 + (jj - 16) * 4);
            *(float4*)(xs[buf] + dstf) = s4[i];
        }
    };

    load_chunk(0, 0);
    __syncthreads();

#pragma unroll 1
    for (int c = 0; c < 8; c++) {
        const int buf = c & 1;
        if (c < 7) load_chunk(c + 1, buf ^ 1);
#pragma unroll 1
        for (int r = 0; r < 32; r++) {
            const ulonglong2* xp = (const ulonglong2*)(xs[buf] + r * 132 + kh * 68);
            u64 a0 = 0, a1 = 0, a2 = 0, a3 = 0;
#pragma unroll
            for (int q = 0; q < 16; q++) {
                ulonglong2 v = xp[q];
                a0 = fma2(w[0][2 * q + 0], v.x, a0);
                a1 = fma2(w[0][2 * q + 1], v.y, a1);
                a2 = fma2(w[1][2 * q + 0], v.x, a2);
                a3 = fma2(w[1][2 * q + 1], v.y, a3);
            }
            float2 f0 = u2f(a0), f1 = u2f(a1), f2_ = u2f(a2), f3 = u2f(a3);
            float s0 = (f0.x + f0.y) + (f1.x + f1.y);
            float s1 = (f2_.x + f2_.y) + (f3.x + f3.y);
            s0 += __shfl_xor_sync(0xffffffffu, s0, 1);
            s1 += __shfl_xor_sync(0xffffffffu, s1, 1);
            if (kh == 0)
                *(float2*)(op + (size_t)(c * 32 + r) * GDIM) =
                    make_float2(s0 + b2.x, s1 + b2.y);
        }
        __syncthreads();
    }
}

// ---------------- recurrence: R3-proven config (1 gate/thread, 5 seqs/CTA, occ 2) ----------------
__global__ __launch_bounds__(192, 2)
void recur_kernel(const float* __restrict__ Whh,   // [2][192][64]
                  const float* __restrict__ bhh)   // [2][192]
{
    const int d   = blockIdx.y;
    const int n0  = blockIdx.x * SPC;
    const int tid = threadIdx.x;

    __shared__ float h_sh[SPC][64];
    __shared__ float s_v[SPC][256];

    u64 w2[32];
    const u64* wr = (const u64*)(Whh + ((size_t)d * GDIM + tid) * HDIM);
#pragma unroll
    for (int q = 0; q < 32; q++) w2[q] = wr[q];
    const float bh = bhh[d * GDIM + tid];

    for (int i = tid; i < SPC * 64; i += 192) ((float*)h_sh)[i] = 0.f;
    __syncthreads();

    const int t0  = d ? (TT - 1) : 0;
    const int dt  = d ? -1 : 1;
    const long dtG = (long)dt * GDIM;

    const float* pcur[SPC];
#pragma unroll
    for (int s = 0; s < SPC; s++) {
        int n = n0 + s;
        int nc = (n < NSEQ) ? n : 0;
        pcur[s] = g_pre + ((size_t)d * MROWS + (size_t)nc * TT + t0) * GDIM + tid;
    }

    const int sA0 = tid / 64;           // 0..2
    const int iA  = tid % 64;
    const int sA1 = sA0 + 3;            // 3..5
    const bool vA0 = (n0 + sA0) < NSEQ;
    const bool vA1 = (sA1 < SPC) && ((n0 + sA1) < NSEQ);
    float* hp0 = g_hbuf + ((size_t)(n0 + sA0) * TT + t0) * 128 + d * 64 + iA;
    float* hp1 = vA1 ? (g_hbuf + ((size_t)(n0 + sA1) * TT + t0) * 128 + d * 64 + iA) : hp0;
    const long dtH = (long)dt * 128;

    float pc[SPC];
#pragma unroll
    for (int s = 0; s < SPC; s++) { pc[s] = __ldg(pcur[s]); pcur[s] += dtG; }

    for (int step = 0; step < TT; step++) {
        float pn[SPC];
        if (step < TT - 1) {
#pragma unroll
            for (int s = 0; s < SPC; s++) { pn[s] = __ldg(pcur[s]); pcur[s] += dtG; }
        }

#pragma unroll
        for (int s = 0; s < SPC; s++) {
            u64 a0 = 0, a1 = 0, a2 = 0, a3 = 0;
            const ulonglong2* h2 = (const ulonglong2*)h_sh[s];
#pragma unroll
            for (int q = 0; q < 16; q += 2) {
                ulonglong2 hv = h2[q];
                ulonglong2 hw = h2[q + 1];
                a0 = fma2(w2[2 * q + 0], hv.x, a0);
                a1 = fma2(w2[2 * q + 1], hv.y, a1);
                a2 = fma2(w2[2 * q + 2], hw.x, a2);
                a3 = fma2(w2[2 * q + 3], hw.y, a3);
            }
            float2 f0 = u2f(a0), f1 = u2f(a1), f2_ = u2f(a2), f3 = u2f(a3);
            float hh = ((f0.x + f0.y) + (f1.x + f1.y)) +
                       ((f2_.x + f2_.y) + (f3.x + f3.y)) + bh;
            if (tid < 128) {
                s_v[s][tid] = hh + pc[s];        // r, z pre-activations
            } else {
                s_v[s][tid]      = hh;           // hn
                s_v[s][tid + 64] = pc[s];        // pn
            }
        }
        __syncthreads();

        {
            const float* sv = s_v[sA0];
            float r    = sig_fast(sv[iA]);
            float z    = sig_fast(sv[64 + iA]);
            float nn   = tanh_fast(sv[192 + iA] + r * sv[128 + iA]);
            float hold = h_sh[sA0][iA];
            float hnew = nn + z * (hold - nn);
            h_sh[sA0][iA] = hnew;
            if (vA0) *hp0 = hnew;
            hp0 += dtH;
        }
        if (sA1 < SPC) {
            const float* sv = s_v[sA1];
            float r    = sig_fast(sv[iA]);
            float z    = sig_fast(sv[64 + iA]);
            float nn   = tanh_fast(sv[192 + iA] + r * sv[128 + iA]);
            float hold = h_sh[sA1][iA];
            float hnew = nn + z * (hold - nn);
            h_sh[sA1][iA] = hnew;
            if (vA1) *hp1 = hnew;
            hp1 += dtH;
        }
        __syncthreads();

#pragma unroll
        for (int s = 0; s < SPC; s++) pc[s] = pn[s];
    }
}

// ---------------- FC head: 2 outputs per warp (MLP=2) ----------------
__global__ void fc_kernel(const float* __restrict__ fcw,
                          const float* __restrict__ fcb,
                          float* __restrict__ out)
{
    int wid  = threadIdx.x >> 5;
    int lane = threadIdx.x & 31;
    size_t g0 = (size_t)blockIdx.x * 16 + wid * 2;

    float4 w4 = *(const float4*)(fcw + lane * 4);
    float4 v0 = *(const float4*)(g_hbuf + g0 * 128 + lane * 4);
    float4 v1 = *(const float4*)(g_hbuf + (g0 + 1) * 128 + lane * 4);
    float d0 = v0.x * w4.x + v0.y * w4.y + v0.z * w4.z + v0.w * w4.w;
    float d1 = v1.x * w4.x + v1.y * w4.y + v1.z * w4.z + v1.w * w4.w;
#pragma unroll
    for (int o = 16; o > 0; o >>= 1) {
        d0 += __shfl_down_sync(0xffffffffu, d0, o);
        d1 += __shfl_down_sync(0xffffffffu, d1, o);
    }
    if (lane == 0) {
        float bb = fcb[0];
#pragma unroll
        for (int k = 0; k < 2; k++) {
            size_t g = g0 + k;
            float dv = k ? d1 : d0;
            int nidx = (int)(g / TT), t = (int)(g % TT);
            int b = nidx / 88, f = nidx % 88;
            out[((size_t)b * TT + t) * 88 + f] = sig_acc(dv + bb);
        }
    }
}

// ---------------- launch ----------------
extern "C" void kernel_launch(void* const* d_in, const int* in_sizes, int n_in,
                              void* d_out, int out_size)
{
    const float* x    = (const float*)d_in[0];
    const float* Wih0 = (const float*)d_in[1];
    const float* Whh0 = (const float*)d_in[2];
    const float* bih0 = (const float*)d_in[3];
    const float* bhh0 = (const float*)d_in[4];
    const float* Wih1 = (const float*)d_in[5];
    const float* Whh1 = (const float*)d_in[6];
    const float* bih1 = (const float*)d_in[7];
    const float* bhh1 = (const float*)d_in[8];
    const float* fcw  = (const float*)d_in[9];
    const float* fcb  = (const float*)d_in[10];
    float* out = (float*)d_out;

    dim3 rg(NCTA_R, 2);

    proj0_kernel<<<MROWS / 256, 192>>>(x, Wih0, bih0);      // L0 input proj
    recur_kernel<<<rg, 192>>>(Whh0, bhh0);                  // L0 GRU
    proj1_kernel<<<MROWS / 256, 384>>>(Wih1, bih1);         // L1 input proj (reads g_hbuf)
    recur_kernel<<<rg, 192>>>(Whh1, bhh1);                  // L1 GRU
    fc_kernel<<<MROWS / 16, 256>>>(fcw, fcb, out);          // FC + sigmoid
}

// round 13
// speedup vs baseline: 1.2643x; 1.0184x over previous
#include <cuda_runtime.h>

// ---------------- problem constants ----------------
#define NSEQ  704          // B*F
#define TT    512
#define HDIM  64
#define GDIM  192          // 3*H
#define MROWS (NSEQ*TT)    // 360448
#define RSPC  3            // sequences per recur CTA (per dir)
#define NCTA_R ((NSEQ + RSPC - 1) / RSPC)   // 235

// ---------------- scratch (device globals; no allocation) ----------------
__device__ float g_pre[(size_t)2 * MROWS * GDIM];   // [dir][row][192]
__device__ float g_hbuf[(size_t)MROWS * 128];       // [row][2*H]

typedef unsigned long long u64;

__device__ __forceinline__ u64 fma2(u64 a, u64 b, u64 c) {
    u64 d;
    asm("fma.rn.f32x2 %0, %1, %2, %3;" : "=l"(d) : "l"(a), "l"(b), "l"(c));
    return d;
}
__device__ __forceinline__ float2 u2f(u64 v) {
    float2 r;
    asm("mov.b64 {%0,%1}, %2;" : "=f"(r.x), "=f"(r.y) : "l"(v));
    return r;
}
__device__ __forceinline__ float tanh_fast(float x) {
    float y;
    asm("tanh.approx.f32 %0, %1;" : "=f"(y) : "f"(x));
    return y;
}
__device__ __forceinline__ float sig_fast(float x) {
    return 0.5f * tanh_fast(0.5f * x) + 0.5f;
}
__device__ __forceinline__ float sig_acc(float x) {
    return __fdividef(1.f, 1.f + __expf(-x));
}

// ---------------- layer-0 projection (KD=64): 2 gate rows per thread ----------------
__global__ __launch_bounds__(192, 2)
void proj0_kernel(const float* __restrict__ xin,
                  const float* __restrict__ W,     // [384][64]
                  const float* __restrict__ bias)  // [384]
{
    const int tid  = threadIdx.x;
    const int row0 = blockIdx.x * 256;

    __shared__ __align__(16) float xs[2][32 * 64];

    const int j0 = 2 * tid;
    const int d  = (j0 >= GDIM) ? 1 : 0;
    const int g0 = j0 - d * GDIM;

    u64 w[2][32];
    const u64* wr = (const u64*)(W + (size_t)j0 * 64);
#pragma unroll
    for (int q = 0; q < 32; q++) { w[0][q] = wr[q]; w[1][q] = wr[32 + q]; }
    const float2 b2 = *(const float2*)(bias + j0);

    float* op = g_pre + ((size_t)d * MROWS + row0) * GDIM + g0;

    {   // chunk 0 (contiguous copy)
        const float4* s4 = (const float4*)(xin + (size_t)row0 * 64);
        for (int i = tid; i < 512; i += 192) ((float4*)xs[0])[i] = s4[i];
    }
    __syncthreads();

#pragma unroll 1
    for (int c = 0; c < 8; c++) {
        const int buf = c & 1;
        if (c < 7) {
            const float4* s4 = (const float4*)(xin + (size_t)(row0 + (c + 1) * 32) * 64);
            for (int i = tid; i < 512; i += 192) ((float4*)xs[buf ^ 1])[i] = s4[i];
        }
#pragma unroll 1
        for (int r = 0; r < 32; r++) {
            const ulonglong2* xp = (const ulonglong2*)(xs[buf] + r * 64);
            u64 a0 = 0, a1 = 0, a2 = 0, a3 = 0;
#pragma unroll
            for (int q = 0; q < 16; q++) {
                ulonglong2 v = xp[q];
                a0 = fma2(w[0][2 * q + 0], v.x, a0);
                a1 = fma2(w[0][2 * q + 1], v.y, a1);
                a2 = fma2(w[1][2 * q + 0], v.x, a2);
                a3 = fma2(w[1][2 * q + 1], v.y, a3);
            }
            float2 f0 = u2f(a0), f1 = u2f(a1), f2_ = u2f(a2), f3 = u2f(a3);
            float s0 = (f0.x + f0.y) + (f1.x + f1.y) + b2.x;
            float s1 = (f2_.x + f2_.y) + (f3.x + f3.y) + b2.y;
            *(float2*)(op + (size_t)(c * 32 + r) * GDIM) = make_float2(s0, s1);
        }
        __syncthreads();
    }
}

// ---------------- layer-1 projection (KD=128): split-K, 2 rows per thread-pair ----------------
__global__ __launch_bounds__(384)
void proj1_kernel(const float* __restrict__ W,     // [384][128]
                  const float* __restrict__ bias)  // [384]
{
    const float* in = (const float*)g_hbuf;
    const int tid  = threadIdx.x;
    const int row0 = blockIdx.x * 256;

    __shared__ __align__(16) float xs[2][32 * 132];   // 132 = 64 + 4 pad + 64

    const int m  = tid >> 1;
    const int kh = tid & 1;
    const int j0 = 2 * m;
    const int d  = (j0 >= GDIM) ? 1 : 0;
    const int g0 = j0 - d * GDIM;

    u64 w[2][32];
    const u64* wr = (const u64*)(W + (size_t)j0 * 128);
#pragma unroll
    for (int q = 0; q < 32; q++) {
        w[0][q] = wr[kh * 32 + q];
        w[1][q] = wr[64 + kh * 32 + q];
    }
    const float2 b2 = *(const float2*)(bias + j0);

    float* op = g_pre + ((size_t)d * MROWS + row0) * GDIM + g0;

    auto load_chunk = [&](int c, int buf) {
        const float4* s4 = (const float4*)(in + (size_t)(row0 + c * 32) * 128);
        for (int i = tid; i < 1024; i += 384) {
            int r = i >> 5, jj = i & 31;
            int dstf = r * 132 + ((jj < 16) ? jj * 4 : 68 + (jj - 16) * 4);
            *(float4*)(xs[buf] + dstf) = s4[i];
        }
    };

    load_chunk(0, 0);
    __syncthreads();

#pragma unroll 1
    for (int c = 0; c < 8; c++) {
        const int buf = c & 1;
        if (c < 7) load_chunk(c + 1, buf ^ 1);
#pragma unroll 1
        for (int r = 0; r < 32; r++) {
            const ulonglong2* xp = (const ulonglong2*)(xs[buf] + r * 132 + kh * 68);
            u64 a0 = 0, a1 = 0, a2 = 0, a3 = 0;
#pragma unroll
            for (int q = 0; q < 16; q++) {
                ulonglong2 v = xp[q];
                a0 = fma2(w[0][2 * q + 0], v.x, a0);
                a1 = fma2(w[0][2 * q + 1], v.y, a1);
                a2 = fma2(w[1][2 * q + 0], v.x, a2);
                a3 = fma2(w[1][2 * q + 1], v.y, a3);
            }
            float2 f0 = u2f(a0), f1 = u2f(a1), f2_ = u2f(a2), f3 = u2f(a3);
            float s0 = (f0.x + f0.y) + (f1.x + f1.y);
            float s1 = (f2_.x + f2_.y) + (f3.x + f3.y);
            s0 += __shfl_xor_sync(0xffffffffu, s0, 1);
            s1 += __shfl_xor_sync(0xffffffffu, s1, 1);
            if (kh == 0)
                *(float2*)(op + (size_t)(c * 32 + r) * GDIM) =
                    make_float2(s0 + b2.x, s1 + b2.y);
        }
        __syncthreads();
    }
}

// ---------------- recurrence v2: 96 threads, 2 gates/thread, SPC=3, occ 4 ----------------
// Thread tid owns gate rows 2tid, 2tid+1 (Whh rows in 128 regs).
// Per seq per step: 16 broadcast LDS.128 + 64 fma2 (1:4 issue ratio, half the
// LDS wavefronts of the 1-gate config). Grid 235x2 = 470 CTAs -> 3.2 CTAs/SM:
// independent CTAs hide each other's barrier/latency stalls.
__global__ __launch_bounds__(96, 4)
void recur_kernel(const float* __restrict__ Whh,   // [2][192][64]
                  const float* __restrict__ bhh)   // [2][192]
{
    const int d   = blockIdx.y;
    const int n0  = blockIdx.x * RSPC;
    const int tid = threadIdx.x;
    const int g0  = 2 * tid;

    __shared__ float h_sh[RSPC][64];
    __shared__ float s_v[RSPC][256];

    u64 w[2][32];
    const u64* wr = (const u64*)(Whh + ((size_t)d * GDIM + g0) * HDIM);
#pragma unroll
    for (int q = 0; q < 32; q++) { w[0][q] = wr[q]; w[1][q] = wr[32 + q]; }
    const float2 bh = *(const float2*)(bhh + d * GDIM + g0);

    ((float*)h_sh)[tid] = 0.f;
    ((float*)h_sh)[tid + 96] = 0.f;
    __syncthreads();

    const int t0  = d ? (TT - 1) : 0;
    const int dt  = d ? -1 : 1;
    const long dtG = (long)dt * GDIM;
    const long dtH = (long)dt * 128;

    // per-seq pre pointers (tail CTA clamps reads to last valid seq)
    const float* pcur[RSPC];
    bool vst[RSPC];
#pragma unroll
    for (int q = 0; q < RSPC; q++) {
        int n = n0 + q;
        vst[q] = (n < NSEQ);
        int nc = vst[q] ? n : (NSEQ - 1);
        pcur[q] = g_pre + ((size_t)d * MROWS + (size_t)nc * TT + t0) * GDIM + g0;
    }

    // activation slots: tid and tid+96 over 192 slots (seq = slot/64, idx = slot%64)
    const int sA0 = tid / 64;            // 0..1
    const int iA0 = tid % 64;
    const int sA1 = (tid + 96) / 64;     // 1..2
    const int iA1 = (tid + 96) % 64;
    const bool vA0 = vst[sA0];
    const bool vA1 = vst[sA1];
    float* hp0 = g_hbuf + ((size_t)(n0 + sA0) * TT + t0) * 128 + d * 64 + iA0;
    float* hp1 = g_hbuf + ((size_t)(n0 + (vA1 ? sA1 : 0)) * TT + t0) * 128 + d * 64 + iA1;

    float2 pc[RSPC];
#pragma unroll
    for (int q = 0; q < RSPC; q++) {
        pc[q] = __ldg((const float2*)pcur[q]);
        pcur[q] += dtG;
    }

#pragma unroll 1
    for (int step = 0; step < TT; step++) {
        float2 pn[RSPC];
        if (step < TT - 1) {
#pragma unroll
            for (int q = 0; q < RSPC; q++) {
                pn[q] = __ldg((const float2*)pcur[q]);
                pcur[q] += dtG;
            }
        }

        // phase A: hh dot products, 2 gates x 3 seqs
#pragma unroll
        for (int seq = 0; seq < RSPC; seq++) {
            const ulonglong2* h2 = (const ulonglong2*)h_sh[seq];
            u64 a0 = 0, a1 = 0, a2 = 0, a3 = 0;
#pragma unroll
            for (int q = 0; q < 16; q++) {
                ulonglong2 v = h2[q];
                a0 = fma2(w[0][2 * q + 0], v.x, a0);
                a1 = fma2(w[0][2 * q + 1], v.y, a1);
                a2 = fma2(w[1][2 * q + 0], v.x, a2);
                a3 = fma2(w[1][2 * q + 1], v.y, a3);
            }
            float2 f0 = u2f(a0), f1 = u2f(a1), f2_ = u2f(a2), f3 = u2f(a3);
            float hh0 = (f0.x + f0.y) + (f1.x + f1.y) + bh.x;
            float hh1 = (f2_.x + f2_.y) + (f3.x + f3.y) + bh.y;
            float2 pcv = pc[seq];
            if (g0 < 128) {      // both gates are r or z: store pre+hh
                *(float2*)&s_v[seq][g0] = make_float2(hh0 + pcv.x, hh1 + pcv.y);
            } else {             // both gates are n: keep hh and pre separate
                *(float2*)&s_v[seq][g0]      = make_float2(hh0, hh1);
                *(float2*)&s_v[seq][g0 + 64] = pcv;
            }
        }
        __syncthreads();

        // phase B: activations, 192 slots over 96 threads (2 each)
        {
            const float* sv = s_v[sA0];
            float r    = sig_fast(sv[iA0]);
            float z    = sig_fast(sv[64 + iA0]);
            float nn   = tanh_fast(sv[192 + iA0] + r * sv[128 + iA0]);
            float hold = h_sh[sA0][iA0];
            float hnew = nn + z * (hold - nn);
            h_sh[sA0][iA0] = hnew;
            if (vA0) *hp0 = hnew;
            hp0 += dtH;
        }
        {
            const float* sv = s_v[sA1];
            float r    = sig_fast(sv[iA1]);
            float z    = sig_fast(sv[64 + iA1]);
            float nn   = tanh_fast(sv[192 + iA1] + r * sv[128 + iA1]);
            float hold = h_sh[sA1][iA1];
            float hnew = nn + z * (hold - nn);
            h_sh[sA1][iA1] = hnew;
            if (vA1) *hp1 = hnew;
            hp1 += dtH;
        }
        __syncthreads();

#pragma unroll
        for (int q = 0; q < RSPC; q++) pc[q] = pn[q];
    }
}

// ---------------- FC head: 2 outputs per warp (MLP=2) ----------------
__global__ void fc_kernel(const float* __restrict__ fcw,
                          const float* __restrict__ fcb,
                          float* __restrict__ out)
{
    int wid  = threadIdx.x >> 5;
    int lane = threadIdx.x & 31;
    size_t g0 = (size_t)blockIdx.x * 16 + wid * 2;

    float4 w4 = *(const float4*)(fcw + lane * 4);
    float4 v0 = *(const float4*)(g_hbuf + g0 * 128 + lane * 4);
    float4 v1 = *(const float4*)(g_hbuf + (g0 + 1) * 128 + lane * 4);
    float d0 = v0.x * w4.x + v0.y * w4.y + v0.z * w4.z + v0.w * w4.w;
    float d1 = v1.x * w4.x + v1.y * w4.y + v1.z * w4.z + v1.w * w4.w;
#pragma unroll
    for (int o = 16; o > 0; o >>= 1) {
        d0 += __shfl_down_sync(0xffffffffu, d0, o);
        d1 += __shfl_down_sync(0xffffffffu, d1, o);
    }
    if (lane == 0) {
        float bb = fcb[0];
#pragma unroll
        for (int k = 0; k < 2; k++) {
            size_t g = g0 + k;
            float dv = k ? d1 : d0;
            int nidx = (int)(g / TT), t = (int)(g % TT);
            int b = nidx / 88, f = nidx % 88;
            out[((size_t)b * TT + t) * 88 + f] = sig_acc(dv + bb);
        }
    }
}

// ---------------- launch ----------------
extern "C" void kernel_launch(void* const* d_in, const int* in_sizes, int n_in,
                              void* d_out, int out_size)
{
    const float* x    = (const float*)d_in[0];
    const float* Wih0 = (const float*)d_in[1];
    const float* Whh0 = (const float*)d_in[2];
    const float* bih0 = (const float*)d_in[3];
    const float* bhh0 = (const float*)d_in[4];
    const float* Wih1 = (const float*)d_in[5];
    const float* Whh1 = (const float*)d_in[6];
    const float* bih1 = (const float*)d_in[7];
    const float* bhh1 = (const float*)d_in[8];
    const float* fcw  = (const float*)d_in[9];
    const float* fcb  = (const float*)d_in[10];
    float* out = (float*)d_out;

    dim3 rg(NCTA_R, 2);

    proj0_kernel<<<MROWS / 256, 192>>>(x, Wih0, bih0);      // L0 input proj
    recur_kernel<<<rg, 96>>>(Whh0, bhh0);                   // L0 GRU
    proj1_kernel<<<MROWS / 256, 384>>>(Wih1, bih1);         // L1 input proj (reads g_hbuf)
    recur_kernel<<<rg, 96>>>(Whh1, bhh1);                   // L1 GRU
    fc_kernel<<<MROWS / 16, 256>>>(fcw, fcb, out);          // FC + sigmoid
}